// round 4
// baseline (speedup 1.0000x reference)
#include <cuda_runtime.h>
#include <math.h>
#include <float.h>

#define D 128
#define KCODES 1024
#define BM 64          // rows per CTA
#define BN 128         // codes per smem chunk
#define SCS 132        // padded row stride (floats) for code tile
#define TM 4           // rows per thread
#define TN 8           // codes per thread
#define NTH 256

__device__ float g_cnorm[KCODES];
__device__ int g_counts[KCODES];
__device__ unsigned long long g_sse;

// packed fp32x2 FMA: d.lo += a.lo*b.lo ; d.hi += a.hi*b.hi  (exact fp32 per lane)
__device__ __forceinline__ void fma2(unsigned long long& d,
                                     unsigned long long a,
                                     unsigned long long b) {
    asm("fma.rn.f32x2 %0, %1, %2, %3;" : "=l"(d) : "l"(a), "l"(b), "l"(d));
}
__device__ __forceinline__ void unpack2(unsigned long long v, float& lo, float& hi) {
    asm("mov.b64 {%0,%1}, %2;" : "=f"(lo), "=f"(hi) : "l"(v));
}

// warp-per-code, coalesced c_norm + zero counts/sse
__global__ void prep_kernel(const float* __restrict__ cb) {
    int tid = blockIdx.x * blockDim.x + threadIdx.x;
    if (tid < KCODES) g_counts[tid] = 0;
    if (tid == 0) g_sse = 0ull;
    int code = tid >> 5;           // one warp per code
    int lane = tid & 31;
    const float4* cb4 = (const float4*)cb;
    float4 v = cb4[(size_t)code * 32 + lane];
    float s = fmaf(v.x, v.x, fmaf(v.y, v.y, fmaf(v.z, v.z, v.w * v.w)));
    #pragma unroll
    for (int off = 16; off; off >>= 1)
        s += __shfl_down_sync(0xffffffffu, s, off);
    if (lane == 0) g_cnorm[code] = s;
}

__global__ __launch_bounds__(NTH) void vq_main(
        const float* __restrict__ x, const float* __restrict__ cb,
        float* __restrict__ out, int nrows) {
    extern __shared__ float smem[];
    float* sx   = smem;                   // BM*D
    float* sc   = sx + BM * D;            // BN*SCS
    float* sxn  = sc + BN * SCS;          // BM
    float* sbv  = sxn + BM;               // BM*16
    int*   sbi  = (int*)(sbv + BM * 16);  // BM*16
    int*   srid = sbi + BM * 16;          // BM

    const int tid = threadIdx.x;
    const int row0 = blockIdx.x * BM;

    // stage x tile: 64 consecutive rows = contiguous 32KB
    float4* sx4 = (float4*)sx;
    const float4* xg4 = (const float4*)(x + (size_t)row0 * D);
    #pragma unroll
    for (int i = tid; i < BM * D / 4; i += NTH) sx4[i] = xg4[i];
    __syncthreads();

    // per-row x norms (serial fmaf chain, matches R1)
    if (tid < BM) {
        const float* r = sx + tid * D;
        float s = 0.f;
        #pragma unroll 8
        for (int d = 0; d < D; ++d) s = fmaf(r[d], r[d], s);
        sxn[tid] = s;
    }
    __syncthreads();

    const int ty = tid >> 4;   // 0..15 row group
    const int tx = tid & 15;   // 0..15 code group

    float xn[TM];
    #pragma unroll
    for (int i = 0; i < TM; ++i) xn[i] = sxn[ty * TM + i];

    float bestv[TM];
    int   besti[TM];
    #pragma unroll
    for (int i = 0; i < TM; ++i) { bestv[i] = FLT_MAX; besti[i] = 0; }

    for (int kc = 0; kc < KCODES; kc += BN) {
        // stage BN codes into padded smem rows
        const float4* cg4 = (const float4*)(cb + (size_t)kc * D);
        #pragma unroll
        for (int i = tid; i < BN * D / 4; i += NTH) {
            int k  = i >> 5;          // 32 float4 per code row
            int d4 = (i & 31) << 2;
            *(float4*)(sc + k * SCS + d4) = cg4[i];
        }
        __syncthreads();

        // packed accumulators: lo half sums even-d terms, hi half odd-d terms
        unsigned long long acc[TM][TN];
        #pragma unroll
        for (int i = 0; i < TM; ++i)
            #pragma unroll
            for (int j = 0; j < TN; ++j) acc[i][j] = 0ull;

        #pragma unroll 4
        for (int d = 0; d < D; d += 4) {
            ulonglong2 ax[TM], cv[TN];
            #pragma unroll
            for (int i = 0; i < TM; ++i)
                ax[i] = *(const ulonglong2*)(sx + (ty * TM + i) * D + d);
            #pragma unroll
            for (int j = 0; j < TN; ++j)
                cv[j] = *(const ulonglong2*)(sc + (tx + 16 * j) * SCS + d);
            #pragma unroll
            for (int i = 0; i < TM; ++i)
                #pragma unroll
                for (int j = 0; j < TN; ++j) {
                    fma2(acc[i][j], ax[i].x, cv[j].x);
                    fma2(acc[i][j], ax[i].y, cv[j].y);
                }
        }

        // score + running argmin; k ascends in j, chunks ascend -> strict <
        // reproduces the reference tie-break (first index wins)
        #pragma unroll
        for (int j = 0; j < TN; ++j) {
            int k = kc + tx + 16 * j;
            float cn = g_cnorm[k];
            #pragma unroll
            for (int i = 0; i < TM; ++i) {
                float lo, hi;
                unpack2(acc[i][j], lo, hi);
                float dot = lo + hi;
                float t = xn[i] + cn;
                float dist = fmaf(-2.0f, dot, t);
                dist = fmaxf(dist, 0.0f);
                if (dist < bestv[i]) { bestv[i] = dist; besti[i] = k; }
            }
        }
        __syncthreads();
    }

    // cross-thread argmin reduction (lexicographic: value, then index)
    #pragma unroll
    for (int i = 0; i < TM; ++i) {
        sbv[(ty * TM + i) * 16 + tx] = bestv[i];
        sbi[(ty * TM + i) * 16 + tx] = besti[i];
    }
    __syncthreads();
    if (tid < BM) {
        float bv = sbv[tid * 16];
        int   bi = sbi[tid * 16];
        #pragma unroll
        for (int j = 1; j < 16; ++j) {
            float v = sbv[tid * 16 + j];
            int  ii = sbi[tid * 16 + j];
            if (v < bv || (v == bv && ii < bi)) { bv = v; bi = ii; }
        }
        srid[tid] = bi;
        atomicAdd(&g_counts[bi], 1);
    }
    __syncthreads();

    // output z_st = x + (z - x), accumulate sum((z-x)^2)
    float lsse = 0.f;
    float4* og4 = (float4*)(out + (size_t)row0 * D);
    #pragma unroll
    for (int i = tid; i < BM * D / 4; i += NTH) {
        int r = i >> 5;
        int idx = srid[r];
        float4 zz = *(const float4*)(cb + (size_t)idx * D + ((i & 31) << 2));
        float4 xx = sx4[i];
        float4 o;
        float t0 = zz.x - xx.x; o.x = xx.x + t0;
        float t1 = zz.y - xx.y; o.y = xx.y + t1;
        float t2 = zz.z - xx.z; o.z = xx.z + t2;
        float t3 = zz.w - xx.w; o.w = xx.w + t3;
        lsse = fmaf(t0, t0, lsse);
        lsse = fmaf(t1, t1, lsse);
        lsse = fmaf(t2, t2, lsse);
        lsse = fmaf(t3, t3, lsse);
        og4[i] = o;
    }

    // deterministic fixed-point SSE accumulation
    #pragma unroll
    for (int off = 16; off; off >>= 1)
        lsse += __shfl_down_sync(0xffffffffu, lsse, off);
    __shared__ float swr[NTH / 32];
    int lane = tid & 31, wid = tid >> 5;
    if (lane == 0) swr[wid] = lsse;
    __syncthreads();
    if (tid == 0) {
        float s = 0.f;
        #pragma unroll
        for (int w = 0; w < NTH / 32; ++w) s += swr[w];
        unsigned long long fx = (unsigned long long)((double)s * 1048576.0 + 0.5);
        atomicAdd(&g_sse, fx);
    }
}

__global__ void finalize_kernel(float* __restrict__ out, int ntot, int nrows) {
    __shared__ float red[32];
    int t = threadIdx.x;
    float p = (float)g_counts[t] / (float)nrows;
    float term = p * logf(p + 1e-10f);
    #pragma unroll
    for (int off = 16; off; off >>= 1)
        term += __shfl_down_sync(0xffffffffu, term, off);
    if ((t & 31) == 0) red[t >> 5] = term;
    __syncthreads();
    if (t < 32) {
        float v = red[t];
        #pragma unroll
        for (int off = 16; off; off >>= 1)
            v += __shfl_down_sync(0xffffffffu, v, off);
        if (t == 0) {
            float sse = (float)((double)g_sse * (1.0 / 1048576.0));
            float loss = sse / (float)ntot;
            out[ntot]     = loss;        // quantization_loss
            out[ntot + 1] = loss;        // commitment_loss (same forward value)
            out[ntot + 2] = expf(-v);    // perplexity
        }
    }
}

extern "C" void kernel_launch(void* const* d_in, const int* in_sizes, int n_in,
                              void* d_out, int out_size) {
    const float* x  = (const float*)d_in[0];
    const float* cb = (const float*)d_in[1];
    float* out = (float*)d_out;
    int ntot  = in_sizes[0];
    int nrows = ntot / D;

    size_t smem_bytes = (size_t)(BM * D + BN * SCS + BM + BM * 16 + BM * 16 + BM)
                        * sizeof(float);
    cudaFuncSetAttribute(vq_main, cudaFuncAttributeMaxDynamicSharedMemorySize,
                         (int)smem_bytes);

    prep_kernel<<<KCODES * 32 / NTH, NTH>>>(cb);
    vq_main<<<nrows / BM, NTH, smem_bytes>>>(x, cb, out, nrows);
    finalize_kernel<<<1, KCODES>>>(out, ntot, nrows);
}

// round 6
// speedup vs baseline: 1.5288x; 1.5288x over previous
#include <cuda_runtime.h>
#include <cuda_bf16.h>
#include <math.h>
#include <float.h>
#include <stdint.h>

#define D 128
#define KC 1024
#define BM 128          // rows per CTA
#define BNC 64          // codes per chunk
#define NCH (KC / BNC)  // 16 chunks
#define KSPL 384        // split-K: [hi | lo | hi] x [hi | hi | lo]
#define KSTEPS (KSPL / 16)
#define NTH 256
#define MARGIN 1e-4f

// ---- smem layout (bytes) ----
#define OFF_A    0                       // 128 x 384 bf16 (768B/row, XOR swizzle) = 98304
#define OFF_B    98304                   // 64 x 384 bf16 = 49152
#define OFF_X    147456                  // 128 x 132 fp32 = 67584
#define OFF_XN   215040                  // 128 f
#define OFF_CN   215552                  // 64 f
#define OFF_RIDX 215808                  // 128 i
#define OFF_SWR  216320                  // 8 f
#define SMEM_TOTAL 216448
#define XSTR 132

__device__ float g_cnorm[KC];
__device__ int g_counts[KC];
__device__ unsigned long long g_sse;
__device__ uint4 g_cbb4[KC * 48];        // bf16 codebook [hi|hi|lo], 768B per code

__device__ __forceinline__ uint32_t smem_u32(const void* p) {
    uint32_t a;
    asm("{ .reg .u64 t; cvta.to.shared.u64 t, %1; cvt.u32.u64 %0, t; }" : "=r"(a) : "l"(p));
    return a;
}
__device__ __forceinline__ void ldsm_x4(uint32_t& r0, uint32_t& r1, uint32_t& r2,
                                        uint32_t& r3, uint32_t addr) {
    asm volatile("ldmatrix.sync.aligned.m8n8.x4.shared.b16 {%0,%1,%2,%3}, [%4];"
                 : "=r"(r0), "=r"(r1), "=r"(r2), "=r"(r3) : "r"(addr));
}
__device__ __forceinline__ void mma16816(float* c, uint32_t a0, uint32_t a1,
                                         uint32_t a2, uint32_t a3,
                                         uint32_t b0, uint32_t b1) {
    asm volatile("mma.sync.aligned.m16n8k16.row.col.f32.bf16.bf16.f32 "
                 "{%0,%1,%2,%3}, {%4,%5,%6,%7}, {%8,%9}, {%0,%1,%2,%3};"
                 : "+f"(c[0]), "+f"(c[1]), "+f"(c[2]), "+f"(c[3])
                 : "r"(a0), "r"(a1), "r"(a2), "r"(a3), "r"(b0), "r"(b1));
}
__device__ __forceinline__ void split2(float a, float b, uint32_t& hi, uint32_t& lo) {
    __nv_bfloat16 ha = __float2bfloat16(a), hb = __float2bfloat16(b);
    __nv_bfloat16 la = __float2bfloat16(a - __bfloat162float(ha));
    __nv_bfloat16 lb = __float2bfloat16(b - __bfloat162float(hb));
    hi = ((uint32_t)__bfloat16_as_ushort(hb) << 16) | __bfloat16_as_ushort(ha);
    lo = ((uint32_t)__bfloat16_as_ushort(lb) << 16) | __bfloat16_as_ushort(la);
}
// top-2 update, strict < keeps earliest index (k iterated ascending)
__device__ __forceinline__ void upd2(float& m1, int& i1, float& m2, int& i2,
                                     float v, int k) {
    if (v < m1) { m2 = m1; i2 = i1; m1 = v; i1 = k; }
    else if (v < m2) { m2 = v; i2 = k; }
}
// lexicographic (value, index) insert for merge
__device__ __forceinline__ void ins2(float& m1, int& i1, float& m2, int& i2,
                                     float v, int k) {
    bool lt1 = (v < m1) || (v == m1 && k < i1);
    if (lt1) { m2 = m1; i2 = i1; m1 = v; i1 = k; }
    else if ((v < m2) || (v == m2 && k < i2)) { m2 = v; i2 = k; }
}
__device__ __forceinline__ float exact_dist(const float* xr, const float* cb,
                                            int k, float xn) {
    const float4* cr = (const float4*)(cb + (size_t)k * D);
    float acc = 0.f;
    #pragma unroll 8
    for (int d4 = 0; d4 < 32; ++d4) {
        float4 c4 = __ldg(cr + d4);
        const float* xp = xr + (d4 << 2);
        acc = fmaf(xp[0], c4.x, acc);
        acc = fmaf(xp[1], c4.y, acc);
        acc = fmaf(xp[2], c4.z, acc);
        acc = fmaf(xp[3], c4.w, acc);
    }
    return fmaxf(fmaf(-2.0f, acc, xn + g_cnorm[k]), 0.0f);
}

// ---------------- prep: c_norm + bf16 codebook + zero counts/sse ----------------
__global__ void prep_kernel(const float* __restrict__ cb) {
    int tid = blockIdx.x * blockDim.x + threadIdx.x;
    if (tid < KC) g_counts[tid] = 0;
    if (tid == 0) g_sse = 0ull;
    int code = tid >> 5;
    int lane = tid & 31;
    const float4* cb4 = (const float4*)cb;
    float4 v = cb4[(size_t)code * 32 + lane];
    // bf16 split, write [hi | hi | lo] row (768B = 192 uint32)
    uint32_t* row = (uint32_t*)&g_cbb4[code * 48];
    uint32_t h01, l01, h23, l23;
    split2(v.x, v.y, h01, l01);
    split2(v.z, v.w, h23, l23);
    int p = lane * 2;                 // uint32 pair index within 64-wide block
    row[p] = h01;       row[p + 1] = h23;
    row[64 + p] = h01;  row[64 + p + 1] = h23;
    row[128 + p] = l01; row[128 + p + 1] = l23;
    // c_norm (warp reduce, as R2 — validated)
    float s = fmaf(v.x, v.x, fmaf(v.y, v.y, fmaf(v.z, v.z, v.w * v.w)));
    #pragma unroll
    for (int off = 16; off; off >>= 1)
        s += __shfl_down_sync(0xffffffffu, s, off);
    if (lane == 0) g_cnorm[code] = s;
}

// ---------------- main ----------------
__global__ __launch_bounds__(NTH, 1) void vq_main(
        const float* __restrict__ x, const float* __restrict__ cb,
        float* __restrict__ out, int nrows) {
    extern __shared__ char smem[];
    const uint32_t sbase = smem_u32(smem);
    float* sxn = (float*)(smem + OFF_XN);
    float* scn = (float*)(smem + OFF_CN);
    int*  ridx = (int*)(smem + OFF_RIDX);

    const int tid = threadIdx.x;
    const int wid = tid >> 5;
    const int lid = tid & 31;
    const int row0 = blockIdx.x * BM;

    // ---- stage A: fp32 x tile + swizzled bf16 [hi|lo|hi] ----
    {
        const float4* xg4 = (const float4*)(x + (size_t)row0 * D);
        #pragma unroll
        for (int i = tid; i < BM * D / 4; i += NTH) {
            int r = i >> 5;
            int d = (i & 31) << 2;
            float4 v = xg4[i];
            *(float4*)(smem + OFF_X + r * 528 + d * 4) = v;
            uint32_t h01, l01, h23, l23;
            split2(v.x, v.y, h01, l01);
            split2(v.z, v.w, h23, l23);
            uint32_t rb = r * 768;
            uint32_t sw = (r & 7) << 4;
            uint32_t k0 = d * 2;          // hi block
            *(uint32_t*)(smem + OFF_A + ((rb + k0) ^ sw))       = h01;
            *(uint32_t*)(smem + OFF_A + ((rb + k0 + 4) ^ sw))   = h23;
            *(uint32_t*)(smem + OFF_A + ((rb + 256 + k0) ^ sw)) = l01;   // lo block
            *(uint32_t*)(smem + OFF_A + ((rb + 256 + k0 + 4) ^ sw)) = l23;
            *(uint32_t*)(smem + OFF_A + ((rb + 512 + k0) ^ sw)) = h01;   // hi copy
            *(uint32_t*)(smem + OFF_A + ((rb + 512 + k0 + 4) ^ sw)) = h23;
        }
    }
    __syncthreads();

    // exact per-row x norms (serial fmaf chain, identical to R1)
    if (tid < BM) {
        const float* r = (const float*)(smem + OFF_X) + tid * XSTR;
        float s = 0.f;
        #pragma unroll 8
        for (int d = 0; d < D; ++d) s = fmaf(r[d], r[d], s);
        sxn[tid] = s;
    }
    __syncthreads();

    const int wr = wid * 16;
    const float xn0 = sxn[wr + (lid >> 2)];
    const float xn1 = sxn[wr + (lid >> 2) + 8];

    // per-lane ldmatrix address bases (XOR swizzle constant per lane)
    const int rowA = wr + (lid & 15);
    const uint32_t swA = (uint32_t)(rowA & 7) << 4;
    const uint32_t aL0 = (uint32_t)(OFF_A + rowA * 768 + ((lid >> 4) << 4));
    const int rBn = lid & 15;
    const uint32_t swB = (uint32_t)(rBn & 7) << 4;
    const uint32_t bL0 = (uint32_t)(OFF_B + rBn * 768 + ((lid >> 4) << 4));

    // filter state: top-2 per row slot
    float m1a = FLT_MAX, m2a = FLT_MAX, m1b = FLT_MAX, m2b = FLT_MAX;
    int i1a = 0, i2a = 0, i1b = 0, i2b = 0;

    for (int ch = 0; ch < NCH; ++ch) {
        const int kc = ch * BNC;
        __syncthreads();   // prior chunk's ldmatrix reads complete
        // stage B chunk: pure 16B copy from bf16 global codebook
        #pragma unroll
        for (int i = tid; i < BNC * 48; i += NTH) {
            int r = i / 48, s = i % 48;
            uint4 v = g_cbb4[(kc + r) * 48 + s];
            uint32_t off = (uint32_t)(r * 768 + s * 16) ^ ((uint32_t)(r & 7) << 4);
            *(uint4*)(smem + OFF_B + off) = v;
        }
        if (tid < BNC) scn[tid] = g_cnorm[kc + tid];
        __syncthreads();

        float acc[8][4];
        #pragma unroll
        for (int t = 0; t < 8; ++t)
            #pragma unroll
            for (int q = 0; q < 4; ++q) acc[t][q] = 0.f;

        #pragma unroll 4
        for (int ks = 0; ks < KSTEPS; ++ks) {
            uint32_t a0, a1, a2, a3;
            ldsm_x4(a0, a1, a2, a3, sbase + ((aL0 + ks * 32) ^ swA));
            #pragma unroll
            for (int p = 0; p < 4; ++p) {
                uint32_t b0, b1, b2, b3;
                ldsm_x4(b0, b1, b2, b3,
                        sbase + ((bL0 + p * 12288 + ks * 32) ^ swB));
                mma16816(acc[2 * p],     a0, a1, a2, a3, b0, b2);
                mma16816(acc[2 * p + 1], a0, a1, a2, a3, b1, b3);
            }
        }

        // filter: approx dist, running top-2 per row slot (k ascending)
        #pragma unroll
        for (int nt = 0; nt < 8; ++nt) {
            int colb = nt * 8 + (lid & 3) * 2;
            float cn0 = scn[colb], cn1 = scn[colb + 1];
            float dv;
            dv = fmaxf(fmaf(-2.f, acc[nt][0], xn0 + cn0), 0.f);
            upd2(m1a, i1a, m2a, i2a, dv, kc + colb);
            dv = fmaxf(fmaf(-2.f, acc[nt][1], xn0 + cn1), 0.f);
            upd2(m1a, i1a, m2a, i2a, dv, kc + colb + 1);
            dv = fmaxf(fmaf(-2.f, acc[nt][2], xn1 + cn0), 0.f);
            upd2(m1b, i1b, m2b, i2b, dv, kc + colb);
            dv = fmaxf(fmaf(-2.f, acc[nt][3], xn1 + cn1), 0.f);
            upd2(m1b, i1b, m2b, i2b, dv, kc + colb + 1);
        }
    }

    // merge top-2 across the 4 lanes of each quad (butterfly)
    #pragma unroll
    for (int off = 1; off <= 2; off <<= 1) {
        float om1 = __shfl_xor_sync(0xffffffffu, m1a, off);
        int   oi1 = __shfl_xor_sync(0xffffffffu, i1a, off);
        float om2 = __shfl_xor_sync(0xffffffffu, m2a, off);
        int   oi2 = __shfl_xor_sync(0xffffffffu, i2a, off);
        ins2(m1a, i1a, m2a, i2a, om1, oi1);
        ins2(m1a, i1a, m2a, i2a, om2, oi2);
        om1 = __shfl_xor_sync(0xffffffffu, m1b, off);
        oi1 = __shfl_xor_sync(0xffffffffu, i1b, off);
        om2 = __shfl_xor_sync(0xffffffffu, m2b, off);
        oi2 = __shfl_xor_sync(0xffffffffu, i2b, off);
        ins2(m1b, i1b, m2b, i2b, om1, oi1);
        ins2(m1b, i1b, m2b, i2b, om2, oi2);
    }

    // refine: exact fp32 recompute (R1 formula), pick winner
    if ((lid & 3) == 0) {
        int r0l = wr + (lid >> 2);
        const float* xr0 = (const float*)(smem + OFF_X) + r0l * XSTR;
        int bi = i1a;
        float bd = exact_dist(xr0, cb, i1a, xn0);
        if (m2a < m1a + MARGIN) {
            float d2 = exact_dist(xr0, cb, i2a, xn0);
            if (d2 < bd || (d2 == bd && i2a < bi)) { bd = d2; bi = i2a; }
        }
        ridx[r0l] = bi;
        atomicAdd(&g_counts[bi], 1);

        int r1l = r0l + 8;
        const float* xr1 = (const float*)(smem + OFF_X) + r1l * XSTR;
        bi = i1b;
        bd = exact_dist(xr1, cb, i1b, xn1);
        if (m2b < m1b + MARGIN) {
            float d2 = exact_dist(xr1, cb, i2b, xn1);
            if (d2 < bd || (d2 == bd && i2b < bi)) { bd = d2; bi = i2b; }
        }
        ridx[r1l] = bi;
        atomicAdd(&g_counts[bi], 1);
    }
    __syncthreads();

    // output z_st = x + (z - x), accumulate sum((z-x)^2)  (identical math to R1)
    float lsse = 0.f;
    float4* og4 = (float4*)(out + (size_t)row0 * D);
    const float4* xg4 = (const float4*)(x + (size_t)row0 * D);
    #pragma unroll
    for (int i = tid; i < BM * D / 4; i += NTH) {
        int r = i >> 5;
        int idx = ridx[r];
        float4 zz = *(const float4*)(cb + (size_t)idx * D + ((i & 31) << 2));
        float4 xx = xg4[i];
        float4 o;
        float t0 = zz.x - xx.x; o.x = xx.x + t0;
        float t1 = zz.y - xx.y; o.y = xx.y + t1;
        float t2 = zz.z - xx.z; o.z = xx.z + t2;
        float t3 = zz.w - xx.w; o.w = xx.w + t3;
        lsse = fmaf(t0, t0, lsse);
        lsse = fmaf(t1, t1, lsse);
        lsse = fmaf(t2, t2, lsse);
        lsse = fmaf(t3, t3, lsse);
        og4[i] = o;
    }

    // deterministic fixed-point SSE accumulation
    #pragma unroll
    for (int off = 16; off; off >>= 1)
        lsse += __shfl_down_sync(0xffffffffu, lsse, off);
    float* swr = (float*)(smem + OFF_SWR);
    if (lid == 0) swr[wid] = lsse;
    __syncthreads();
    if (tid == 0) {
        float s = 0.f;
        #pragma unroll
        for (int w = 0; w < NTH / 32; ++w) s += swr[w];
        unsigned long long fx = (unsigned long long)((double)s * 1048576.0 + 0.5);
        atomicAdd(&g_sse, fx);
    }
}

__global__ void finalize_kernel(float* __restrict__ out, int ntot, int nrows) {
    __shared__ float red[32];
    int t = threadIdx.x;
    float p = (float)g_counts[t] / (float)nrows;
    float term = p * logf(p + 1e-10f);
    #pragma unroll
    for (int off = 16; off; off >>= 1)
        term += __shfl_down_sync(0xffffffffu, term, off);
    if ((t & 31) == 0) red[t >> 5] = term;
    __syncthreads();
    if (t < 32) {
        float v = red[t];
        #pragma unroll
        for (int off = 16; off; off >>= 1)
            v += __shfl_down_sync(0xffffffffu, v, off);
        if (t == 0) {
            float sse = (float)((double)g_sse * (1.0 / 1048576.0));
            float loss = sse / (float)ntot;
            out[ntot]     = loss;        // quantization_loss
            out[ntot + 1] = loss;        // commitment_loss (same forward value)
            out[ntot + 2] = expf(-v);    // perplexity
        }
    }
}

extern "C" void kernel_launch(void* const* d_in, const int* in_sizes, int n_in,
                              void* d_out, int out_size) {
    const float* x  = (const float*)d_in[0];
    const float* cb = (const float*)d_in[1];
    float* out = (float*)d_out;
    int ntot  = in_sizes[0];
    int nrows = ntot / D;

    cudaFuncSetAttribute(vq_main, cudaFuncAttributeMaxDynamicSharedMemorySize,
                         SMEM_TOTAL);

    prep_kernel<<<KC * 32 / NTH, NTH>>>(cb);
    vq_main<<<nrows / BM, NTH, SMEM_TOTAL>>>(x, cb, out, nrows);
    finalize_kernel<<<1, KC>>>(out, ntot, nrows);
}